// round 11
// baseline (speedup 1.0000x reference)
#include <cuda_runtime.h>
#include <math.h>
#include <stdint.h>

#define NACC_MAX 200000
#define NMER_MAX 100000
#define E_MAX    500000

// ---------------- scratch (device globals; no allocations allowed) -------------
__device__ float    g_xa[(size_t)NACC_MAX * 128];
__device__ float    g_xm[(size_t)NMER_MAX * 128];
__device__ float    g_ya[(size_t)NACC_MAX * 128];
__device__ float    g_ym[(size_t)NMER_MAX * 128];
__device__ uint32_t g_xah[(size_t)NACC_MAX * 64];     // xdst split (accounts)
__device__ uint32_t g_xal[(size_t)NACC_MAX * 64];
__device__ uint32_t g_xmh[(size_t)NMER_MAX * 64];     // xdst split (merchants)
__device__ uint32_t g_xml[(size_t)NMER_MAX * 64];
__device__ uint32_t g_wh[8 * 128 * 128];              // pre-split weights, 8 slots
__device__ uint32_t g_wl[8 * 128 * 128];
__device__ int   g_rowptr[3][NACC_MAX + 1];
__device__ int   g_csr[3][E_MAX];
__device__ int   g_deg[3][NACC_MAX];
__device__ int   g_cur[3][NACC_MAX];
__device__ int   g_bsum[3][1024];
__device__ float g_stat[4 * 128];   // [sum_a | sqs_a | sum_m | sqs_m]

// ---------------- bf16x3 emulation helpers ---------------------------------------
__device__ __forceinline__ void split2(float2 v, uint32_t& h, uint32_t& l) {
    uint32_t u0 = __float_as_uint(v.x), u1 = __float_as_uint(v.y);
    h = __byte_perm(u0, u1, 0x7632);
    float r0 = v.x - __uint_as_float(u0 & 0xFFFF0000u);
    float r1 = v.y - __uint_as_float(u1 & 0xFFFF0000u);
    asm("cvt.rn.bf16x2.f32 %0, %1, %2;" : "=r"(l) : "f"(r1), "f"(r0));
}

__device__ __forceinline__ void mma_bf16(float* d, const uint32_t* a,
                                         uint32_t b0, uint32_t b1) {
    asm volatile(
        "mma.sync.aligned.m16n8k16.row.col.f32.bf16.bf16.f32 "
        "{%0,%1,%2,%3}, {%4,%5,%6,%7}, {%8,%9}, {%0,%1,%2,%3};"
        : "+f"(d[0]), "+f"(d[1]), "+f"(d[2]), "+f"(d[3])
        : "r"(a[0]), "r"(a[1]), "r"(a[2]), "r"(a[3]), "r"(b0), "r"(b1));
}

__device__ __forceinline__ uint32_t saddr(const void* p) {
    uint32_t a;
    asm("{ .reg .u64 t; cvta.to.shared.u64 t, %1; cvt.u32.u64 %0, t; }"
        : "=r"(a) : "l"(p));
    return a;
}

__device__ __forceinline__ void cp16(uint32_t dst, const void* src, bool pred) {
    asm volatile("cp.async.cg.shared.global [%0], [%1], 16, %2;"
                 :: "r"(dst), "l"(src), "r"(pred ? 16 : 0) : "memory");
}
__device__ __forceinline__ void cp_commit() {
    asm volatile("cp.async.commit_group;" ::: "memory");
}

// ---------------- CSR build ------------------------------------------------------
__global__ void hist_kernel(const int* __restrict__ ei, int E, int* __restrict__ deg) {
    int e = blockIdx.x * blockDim.x + threadIdx.x;
    if (e >= E) return;
    atomicAdd(&deg[ei[E + e]], 1);
}

__global__ void scan1(const int* __restrict__ deg, int n,
                      int* __restrict__ rowptr, int* __restrict__ bsum) {
    __shared__ int s[1024];
    int i = blockIdx.x * 1024 + threadIdx.x;
    int v = (i < n) ? deg[i] : 0;
    s[threadIdx.x] = v;
    __syncthreads();
    for (int off = 1; off < 1024; off <<= 1) {
        int t = (threadIdx.x >= off) ? s[threadIdx.x - off] : 0;
        __syncthreads();
        s[threadIdx.x] += t;
        __syncthreads();
    }
    if (i < n) rowptr[i + 1] = s[threadIdx.x];
    if (threadIdx.x == 1023) bsum[blockIdx.x] = s[1023];
}

__global__ void scan2(int* __restrict__ bsum, int nb) {
    __shared__ int s[1024];
    int v = (threadIdx.x < nb) ? bsum[threadIdx.x] : 0;
    s[threadIdx.x] = v;
    __syncthreads();
    for (int off = 1; off < 1024; off <<= 1) {
        int t = (threadIdx.x >= off) ? s[threadIdx.x - off] : 0;
        __syncthreads();
        s[threadIdx.x] += t;
        __syncthreads();
    }
    if (threadIdx.x < nb) bsum[threadIdx.x] = s[threadIdx.x] - v;  // exclusive
}

__global__ void scan3(int n, int* __restrict__ rowptr, const int* __restrict__ bsum) {
    int i = blockIdx.x * blockDim.x + threadIdx.x;
    if (i < n) rowptr[i + 1] += bsum[i >> 10];
    if (i == 0) rowptr[0] = 0;
}

__global__ void scatter_kernel(const int* __restrict__ ei, int E,
                               int* __restrict__ cur, int* __restrict__ csr) {
    int e = blockIdx.x * blockDim.x + threadIdx.x;
    if (e >= E) return;
    int src = ei[e], dst = ei[E + e];
    int pos = atomicAdd(&cur[dst], 1);
    csr[pos] = src;
}

// ---------------- weight split: [Wl|Wr] fp32 -> packed bf16x2 hi/lo --------------
__global__ void split_w(const float* __restrict__ W1, const float* __restrict__ W2,
                        uint32_t* __restrict__ Bh, uint32_t* __restrict__ Bl, int DO)
{
    int idx = blockIdx.x * 256 + threadIdx.x;
    if (idx >= DO * 128) return;
    int j = idx >> 7, p = idx & 127;
    const float* W = (p < 64) ? W1 + (size_t)j * 128 + 2 * p
                              : W2 + (size_t)j * 128 + 2 * (p - 64);
    uint32_t h, l;
    split2(make_float2(W[0], W[1]), h, l);
    Bh[idx] = h; Bl[idx] = l;
}

// ---------------- fused SAGE: gather+mean+split -> bf16x3 GEMM -------------------
// D[128, DO] per CTA = [mean_agg | xdst][128, 256] @ B[DO, 256]^T
// Gather phase: warp per 8 dst rows, fp32 mean from xsrc via CSR, pre-split into
// smem A panel Agh/Agl [128][64] (stride 68 => frag banks 4g+t, conflict-free).
// k-tiles 0-7 read the smem panel (no cp.async); 8-15 stream pre-split xdst.
// Epilogue = +bias, row L2-norm, optional += (HeteroConv), optional BN stats.
#define AGH_OFF 0
#define AGL_OFF 8704                    // 128*68
#define BR_OFF  17408
#define AR_OFF  25088                   // BR + 3*2560
#define FL_OFF  32768                   // AR + 3*2560
#define SMEM_FUSED ((FL_OFF + 512) * 4)

template<int DO, bool ACCUM, bool STATS>
__global__ __launch_bounds__(512)
void sage_fused(int n,
                const int* __restrict__ rp, const int* __restrict__ cs,
                const float* __restrict__ xsrc,
                const uint32_t* __restrict__ Xh, const uint32_t* __restrict__ Xl,
                const uint32_t* __restrict__ Bh, const uint32_t* __restrict__ Bl,
                const float* __restrict__ bias, float* __restrict__ C,
                float* __restrict__ gsum, float* __restrict__ gsqs)
{
    constexpr int NJ = DO / 32;
    extern __shared__ uint32_t smu[];
    uint32_t* Agh = smu + AGH_OFF;      // [128][68]
    uint32_t* Agl = smu + AGL_OFF;
    uint32_t* Br  = smu + BR_OFF;       // [3][128][20]
    uint32_t* Ar  = smu + AR_OFF;       // [3][128][20]
    float* sBias = reinterpret_cast<float*>(smu + FL_OFF);
    float* ssRow = sBias + 128;
    float* sCS   = ssRow + 128;
    float* sCQ   = sCS + 128;

    int tid = threadIdx.x, lane = tid & 31, warp = tid >> 5;
    int g = lane >> 2, t = lane & 3;
    int wm = warp & 3, wn = warp >> 2;
    int row0 = blockIdx.x * 128;

    if (tid < DO) {
        sBias[tid] = bias[tid];
        if (STATS) { sCS[tid] = 0.f; sCQ[tid] = 0.f; }
    }
    if (tid < 128) ssRow[tid] = 0.f;

    auto load_B = [&](int kt, int slot) {
        if (tid < DO * 4) {
            int j = tid >> 2, q = tid & 3;
            const uint32_t* src = ((q < 2) ? Bh : Bl)
                                + (size_t)j * 128 + kt * 8 + (q & 1) * 4;
            cp16(saddr(Br + slot * 2560 + j * 20 + q * 4), src, true);
        }
    };
    auto load_A = [&](int kt, int slot) {   // kt >= 8: pre-split xdst
        int m = tid >> 2, q = tid & 3;
        int pairBase = (kt - 8) * 8;
        int r = row0 + m;
        bool p = (r < n);
        int rc = p ? r : 0;
        const uint32_t* src = ((q < 2) ? Xh : Xl)
                            + (size_t)rc * 64 + pairBase + (q & 1) * 4;
        cp16(saddr(Ar + slot * 2560 + m * 20 + q * 4), src, p);
    };

    // issue first two B tiles before the gather so they are hidden behind it
    load_B(0, 0); cp_commit();
    load_B(1, 1); cp_commit();

    // ---- gather phase: warp handles rows warp*8 .. warp*8+7 ----
#pragma unroll 1
    for (int r8 = 0; r8 < 8; r8++) {
        int row = warp * 8 + r8;
        int gr = row0 + row;
        float4 acc = make_float4(0.f, 0.f, 0.f, 0.f);
        if (gr < n) {
            int s = __ldg(&rp[gr]), e = __ldg(&rp[gr + 1]);
            int i = s;
            for (; i + 2 <= e; i += 2) {
                int s0 = __ldg(&cs[i]), s1 = __ldg(&cs[i + 1]);
                float4 v0 = __ldg(reinterpret_cast<const float4*>(xsrc + (size_t)s0 * 128) + lane);
                float4 v1 = __ldg(reinterpret_cast<const float4*>(xsrc + (size_t)s1 * 128) + lane);
                acc.x += v0.x + v1.x; acc.y += v0.y + v1.y;
                acc.z += v0.z + v1.z; acc.w += v0.w + v1.w;
            }
            if (i < e) {
                int s0 = __ldg(&cs[i]);
                float4 v0 = __ldg(reinterpret_cast<const float4*>(xsrc + (size_t)s0 * 128) + lane);
                acc.x += v0.x; acc.y += v0.y; acc.z += v0.z; acc.w += v0.w;
            }
            float inv = 1.f / fmaxf((float)(e - s), 1.f);
            acc.x *= inv; acc.y *= inv; acc.z *= inv; acc.w *= inv;
        }
        uint32_t h0, l0, h1, l1;
        split2(make_float2(acc.x, acc.y), h0, l0);
        split2(make_float2(acc.z, acc.w), h1, l1);
        *reinterpret_cast<uint2*>(Agh + row * 68 + 2 * lane) = make_uint2(h0, h1);
        *reinterpret_cast<uint2*>(Agl + row * 68 + 2 * lane) = make_uint2(l0, l1);
    }
    __syncthreads();

    float acc[2][NJ][4];
#pragma unroll
    for (int i = 0; i < 2; i++)
#pragma unroll
        for (int j = 0; j < NJ; j++)
#pragma unroll
            for (int c = 0; c < 4; c++) acc[i][j][c] = 0.f;

    // ---- mainloop: 16 k-tiles of 16 ----
    for (int kt = 0; kt < 16; kt++) {
        if (kt + 1 < 16) asm volatile("cp.async.wait_group 1;" ::: "memory");
        else             asm volatile("cp.async.wait_group 0;" ::: "memory");
        __syncthreads();
        if (kt + 2 < 16) {
            load_B(kt + 2, (kt + 2) % 3);
            if (kt + 2 >= 8) load_A(kt + 2, (kt + 2) % 3);
            cp_commit();
        }

        uint32_t ah[2][4], al[2][4];
        if (kt < 8) {
            int base = kt * 8 + t;
#pragma unroll
            for (int i = 0; i < 2; i++) {
                int rb = wm * 32 + i * 16;
                ah[i][0] = Agh[(rb + g) * 68 + base];
                ah[i][1] = Agh[(rb + g + 8) * 68 + base];
                ah[i][2] = Agh[(rb + g) * 68 + base + 4];
                ah[i][3] = Agh[(rb + g + 8) * 68 + base + 4];
                al[i][0] = Agl[(rb + g) * 68 + base];
                al[i][1] = Agl[(rb + g + 8) * 68 + base];
                al[i][2] = Agl[(rb + g) * 68 + base + 4];
                al[i][3] = Agl[(rb + g + 8) * 68 + base + 4];
            }
        } else {
            const uint32_t* As = Ar + (kt % 3) * 2560;
#pragma unroll
            for (int i = 0; i < 2; i++) {
                int rb = wm * 32 + i * 16;
                ah[i][0] = As[(rb + g) * 20 + t];
                ah[i][1] = As[(rb + g + 8) * 20 + t];
                ah[i][2] = As[(rb + g) * 20 + t + 4];
                ah[i][3] = As[(rb + g + 8) * 20 + t + 4];
                al[i][0] = As[(rb + g) * 20 + t + 8];
                al[i][1] = As[(rb + g + 8) * 20 + t + 8];
                al[i][2] = As[(rb + g) * 20 + t + 12];
                al[i][3] = As[(rb + g + 8) * 20 + t + 12];
            }
        }
        const uint32_t* Bs = Br + (kt % 3) * 2560;
#pragma unroll
        for (int j = 0; j < NJ; j++) {
            int nb = wn * (NJ * 8) + j * 8 + g;
            uint32_t bh0 = Bs[nb * 20 + t];
            uint32_t bh1 = Bs[nb * 20 + t + 4];
            uint32_t bl0 = Bs[nb * 20 + t + 8];
            uint32_t bl1 = Bs[nb * 20 + t + 12];
#pragma unroll
            for (int i = 0; i < 2; i++) {
                mma_bf16(acc[i][j], ah[i], bh0, bh1);
                mma_bf16(acc[i][j], ah[i], bl0, bl1);
                mma_bf16(acc[i][j], al[i], bh0, bh1);
            }
        }
        __syncthreads();
    }

    // ---- epilogue: bias, row L2-norm, accumulate, fused BN stats ----
#pragma unroll
    for (int i = 0; i < 2; i++) {
        float ss0 = 0.f, ss1 = 0.f;
#pragma unroll
        for (int j = 0; j < NJ; j++) {
            int cb = wn * (NJ * 8) + j * 8 + t * 2;
            float b0 = sBias[cb], b1 = sBias[cb + 1];
            acc[i][j][0] += b0; acc[i][j][1] += b1;
            acc[i][j][2] += b0; acc[i][j][3] += b1;
            ss0 += acc[i][j][0] * acc[i][j][0] + acc[i][j][1] * acc[i][j][1];
            ss1 += acc[i][j][2] * acc[i][j][2] + acc[i][j][3] * acc[i][j][3];
        }
        ss0 += __shfl_xor_sync(0xffffffffu, ss0, 1);
        ss0 += __shfl_xor_sync(0xffffffffu, ss0, 2);
        ss1 += __shfl_xor_sync(0xffffffffu, ss1, 1);
        ss1 += __shfl_xor_sync(0xffffffffu, ss1, 2);
        if (t == 0) {
            atomicAdd(&ssRow[wm * 32 + i * 16 + g], ss0);
            atomicAdd(&ssRow[wm * 32 + i * 16 + g + 8], ss1);
        }
    }
    __syncthreads();

    float cs2[NJ][2], cq2[NJ][2];
    if (STATS) {
#pragma unroll
        for (int j = 0; j < NJ; j++) { cs2[j][0] = cs2[j][1] = cq2[j][0] = cq2[j][1] = 0.f; }
    }

#pragma unroll
    for (int i = 0; i < 2; i++) {
        int rl = wm * 32 + i * 16 + g;
        float s0 = 1.f / fmaxf(sqrtf(ssRow[rl]), 1e-12f);
        float s1 = 1.f / fmaxf(sqrtf(ssRow[rl + 8]), 1e-12f);
        int r0 = row0 + rl, r1 = r0 + 8;
#pragma unroll
        for (int j = 0; j < NJ; j++) {
            int cb = wn * (NJ * 8) + j * 8 + t * 2;
            if (r0 < n) {
                float2* p = reinterpret_cast<float2*>(C + (size_t)r0 * DO + cb);
                float2 v = make_float2(acc[i][j][0] * s0, acc[i][j][1] * s0);
                if (ACCUM) { float2 o = *p; v.x += o.x; v.y += o.y; }
                *p = v;
                if (STATS) {
                    cs2[j][0] += v.x; cs2[j][1] += v.y;
                    cq2[j][0] += v.x * v.x; cq2[j][1] += v.y * v.y;
                }
            }
            if (r1 < n) {
                float2* p = reinterpret_cast<float2*>(C + (size_t)r1 * DO + cb);
                float2 v = make_float2(acc[i][j][2] * s1, acc[i][j][3] * s1);
                if (ACCUM) { float2 o = *p; v.x += o.x; v.y += o.y; }
                *p = v;
                if (STATS) {
                    cs2[j][0] += v.x; cs2[j][1] += v.y;
                    cq2[j][0] += v.x * v.x; cq2[j][1] += v.y * v.y;
                }
            }
        }
    }

    if (STATS) {
#pragma unroll
        for (int j = 0; j < NJ; j++)
#pragma unroll
            for (int c = 0; c < 2; c++) {
                float s = cs2[j][c], q = cq2[j][c];
                s += __shfl_xor_sync(0xffffffffu, s, 4);
                s += __shfl_xor_sync(0xffffffffu, s, 8);
                s += __shfl_xor_sync(0xffffffffu, s, 16);
                q += __shfl_xor_sync(0xffffffffu, q, 4);
                q += __shfl_xor_sync(0xffffffffu, q, 8);
                q += __shfl_xor_sync(0xffffffffu, q, 16);
                if (g == 0) {
                    int cb = wn * (NJ * 8) + j * 8 + t * 2 + c;
                    atomicAdd(&sCS[cb], s);
                    atomicAdd(&sCQ[cb], q);
                }
            }
        __syncthreads();
        if (tid < DO) {
            atomicAdd(&gsum[tid], sCS[tid]);
            atomicAdd(&gsqs[tid], sCQ[tid]);
        }
    }
}

// ---------------- projection GEMM (split-in-loop, R10 proven) --------------------
#define TILE_U 2560
#define SMEM_PROJ ((6 * TILE_U + 512) * 4)

__global__ __launch_bounds__(512)
void proj_gemm(int n, int K,
               const float* __restrict__ A1, const float* __restrict__ B1,
               const float* __restrict__ bias, float* __restrict__ C,
               uint32_t* __restrict__ Ch, uint32_t* __restrict__ Cl)
{
    constexpr int DO = 128, NJ = 4;
    extern __shared__ float smf[];
    float* AsBase = smf;
    float* BsBase = smf + 3 * TILE_U;
    float* sBias  = smf + 6 * TILE_U;

    int tid = threadIdx.x, lane = tid & 31, warp = tid >> 5;
    int g = lane >> 2, t = lane & 3;
    int wm = warp & 3, wn = warp >> 2;
    int row0 = blockIdx.x * 128;

    if (tid < DO) sBias[tid] = bias[tid];

    float acc[2][NJ][4];
#pragma unroll
    for (int i = 0; i < 2; i++)
#pragma unroll
        for (int j = 0; j < NJ; j++)
#pragma unroll
            for (int c = 0; c < 4; c++) acc[i][j][c] = 0.f;

    const int T = K >> 4;

    auto load_tile = [&](int kt, int buf) {
        {
            int m = tid >> 2, q = tid & 3, k = kt * 16 + q * 4;
            int r = row0 + m;
            bool p = (r < n);
            int rc = p ? r : 0;
            cp16(saddr(AsBase + buf * TILE_U + m * 20 + q * 4),
                 A1 + (size_t)rc * K + k, p);
        }
        {
            int j = tid >> 2, q = tid & 3, k = kt * 16 + q * 4;
            cp16(saddr(BsBase + buf * TILE_U + j * 20 + q * 4),
                 B1 + (size_t)j * K + k, true);
        }
    };

    auto compute = [&](int buf) {
        const float* As = AsBase + buf * TILE_U;
        const float* Bs = BsBase + buf * TILE_U;
        uint32_t ah[2][4], al[2][4];
#pragma unroll
        for (int i = 0; i < 2; i++) {
            int rb = wm * 32 + i * 16;
            float2 v0 = *reinterpret_cast<const float2*>(As + (rb + g) * 20 + 2 * t);
            float2 v1 = *reinterpret_cast<const float2*>(As + (rb + g + 8) * 20 + 2 * t);
            float2 v2 = *reinterpret_cast<const float2*>(As + (rb + g) * 20 + 2 * t + 8);
            float2 v3 = *reinterpret_cast<const float2*>(As + (rb + g + 8) * 20 + 2 * t + 8);
            split2(v0, ah[i][0], al[i][0]);
            split2(v1, ah[i][1], al[i][1]);
            split2(v2, ah[i][2], al[i][2]);
            split2(v3, ah[i][3], al[i][3]);
        }
#pragma unroll
        for (int j = 0; j < NJ; j++) {
            int nb = wn * (NJ * 8) + j * 8 + g;
            float2 w0 = *reinterpret_cast<const float2*>(Bs + nb * 20 + 2 * t);
            float2 w1 = *reinterpret_cast<const float2*>(Bs + nb * 20 + 2 * t + 8);
            uint32_t bh0, bl0, bh1, bl1;
            split2(w0, bh0, bl0);
            split2(w1, bh1, bl1);
#pragma unroll
            for (int i = 0; i < 2; i++) {
                mma_bf16(acc[i][j], ah[i], bh0, bh1);
                mma_bf16(acc[i][j], ah[i], bl0, bl1);
                mma_bf16(acc[i][j], al[i], bh0, bh1);
            }
        }
    };

    load_tile(0, 0); cp_commit();
    if (T > 1) { load_tile(1, 1); cp_commit(); }
    for (int kt = 0; kt < T; kt++) {
        if (kt + 1 < T) asm volatile("cp.async.wait_group 1;" ::: "memory");
        else            asm volatile("cp.async.wait_group 0;" ::: "memory");
        __syncthreads();
        if (kt + 2 < T) { load_tile(kt + 2, (kt + 2) % 3); cp_commit(); }
        compute(kt % 3);
        __syncthreads();
    }

    // epilogue: +bias, store fp32 + pre-split hi/lo
#pragma unroll
    for (int i = 0; i < 2; i++) {
        int rl = wm * 32 + i * 16 + g;
        int r0 = row0 + rl, r1 = r0 + 8;
#pragma unroll
        for (int j = 0; j < NJ; j++) {
            int cb = wn * (NJ * 8) + j * 8 + t * 2;
            float b0 = sBias[cb], b1 = sBias[cb + 1];
            if (r0 < n) {
                float2 v = make_float2(acc[i][j][0] + b0, acc[i][j][1] + b1);
                *reinterpret_cast<float2*>(C + (size_t)r0 * DO + cb) = v;
                uint32_t h, l; split2(v, h, l);
                Ch[(size_t)r0 * 64 + cb / 2] = h;
                Cl[(size_t)r0 * 64 + cb / 2] = l;
            }
            if (r1 < n) {
                float2 v = make_float2(acc[i][j][2] + b0, acc[i][j][3] + b1);
                *reinterpret_cast<float2*>(C + (size_t)r1 * DO + cb) = v;
                uint32_t h, l; split2(v, h, l);
                Ch[(size_t)r1 * 64 + cb / 2] = h;
                Cl[(size_t)r1 * 64 + cb / 2] = l;
            }
        }
    }
}

// ---------------- BatchNorm apply: fp32 out + pre-split hi/lo --------------------
__global__ void bn_apply_kernel(const float* __restrict__ X, float* __restrict__ Y,
                                uint32_t* __restrict__ Yh, uint32_t* __restrict__ Yl,
                                int n, int d,
                                const float* __restrict__ sum, const float* __restrict__ sqs,
                                const float* __restrict__ g, const float* __restrict__ b,
                                int relu)
{
    int d4 = d >> 2;
    size_t total = (size_t)n * d4;
    float invn = 1.f / (float)n;
    for (size_t i = blockIdx.x * (size_t)blockDim.x + threadIdx.x; i < total;
         i += (size_t)gridDim.x * blockDim.x) {
        int c = (int)(i % d4) * 4;
        float4 x = *(reinterpret_cast<const float4*>(X) + i);
        float4 y;
#pragma unroll
        for (int k = 0; k < 4; k++) {
            float mu = sum[c + k] * invn;
            float var = sqs[c + k] * invn - mu * mu;
            float xv = (&x.x)[k];
            float yv = (xv - mu) * rsqrtf(var + 1e-5f) * g[c + k] + b[c + k];
            if (relu) yv = fmaxf(yv, 0.f);
            (&y.x)[k] = yv;
        }
        *(reinterpret_cast<float4*>(Y) + i) = y;
        if (Yh) {
            uint32_t h0, l0, h1, l1;
            split2(make_float2(y.x, y.y), h0, l0);
            split2(make_float2(y.z, y.w), h1, l1);
            *reinterpret_cast<uint2*>(Yh + i * 2) = make_uint2(h0, h1);
            *reinterpret_cast<uint2*>(Yl + i * 2) = make_uint2(l0, l1);
        }
    }
}

// ---------------- fused classifier: relu(x@W1^T+b1)@W2^T+b2 --------------------
__global__ __launch_bounds__(256)
void classifier_kernel(const float* __restrict__ X, int n,
                       const float* __restrict__ W1, const float* __restrict__ b1,
                       const float* __restrict__ W2, const float* __restrict__ b2,
                       float* __restrict__ out)
{
    __shared__ float sW1[64 * 65];
    __shared__ float sW2[64];
    __shared__ float sb1[64];
    int tid = threadIdx.x;
    for (int i = tid; i < 64 * 64; i += 256) {
        int j = i >> 6, k = i & 63;
        sW1[j * 65 + k] = W1[i];
    }
    if (tid < 64) { sW2[tid] = W2[tid]; sb1[tid] = b1[tid]; }
    __syncthreads();

    int lane = tid & 31;
    int row = blockIdx.x * 8 + (tid >> 5);
    if (row >= n) return;
    float x0 = X[(size_t)row * 64 + lane];
    float x1 = X[(size_t)row * 64 + 32 + lane];
    float h0 = sb1[lane], h1 = sb1[lane + 32];
#pragma unroll
    for (int k = 0; k < 32; k++) {
        float xk = __shfl_sync(0xffffffffu, x0, k);
        h0 += xk * sW1[lane * 65 + k];
        h1 += xk * sW1[(lane + 32) * 65 + k];
    }
#pragma unroll
    for (int k = 0; k < 32; k++) {
        float xk = __shfl_sync(0xffffffffu, x1, k);
        h0 += xk * sW1[lane * 65 + 32 + k];
        h1 += xk * sW1[(lane + 32) * 65 + 32 + k];
    }
    h0 = fmaxf(h0, 0.f); h1 = fmaxf(h1, 0.f);
    float p = h0 * sW2[lane] + h1 * sW2[lane + 32];
#pragma unroll
    for (int off = 16; off; off >>= 1)
        p += __shfl_xor_sync(0xffffffffu, p, off);
    if (lane == 0) out[row] = p + b2[0];
}

// ---------------- kernel_launch -------------------------------------------------
extern "C" void kernel_launch(void* const* d_in, const int* in_sizes, int n_in,
                              void* d_out, int out_size)
{
    const float* x_acc      = (const float*)d_in[0];
    const float* x_mer      = (const float*)d_in[1];
    const int*   ei[3]      = {(const int*)d_in[2], (const int*)d_in[3], (const int*)d_in[4]};
    const float* projW_acc  = (const float*)d_in[5];
    const float* projb_acc  = (const float*)d_in[6];
    const float* projW_mer  = (const float*)d_in[7];
    const float* projb_mer  = (const float*)d_in[8];
    const float* Wl[3] = {(const float*)d_in[9],  (const float*)d_in[12], (const float*)d_in[15]};
    const float* bl[3] = {(const float*)d_in[10], (const float*)d_in[13], (const float*)d_in[16]};
    const float* Wr[3] = {(const float*)d_in[11], (const float*)d_in[14], (const float*)d_in[17]};
    const float* bng[3] = {(const float*)d_in[18], (const float*)d_in[20], (const float*)d_in[22]};
    const float* bnb[3] = {(const float*)d_in[19], (const float*)d_in[21], (const float*)d_in[23]};
    const float* clfW1 = (const float*)d_in[24];
    const float* clfb1 = (const float*)d_in[25];
    const float* clfW2 = (const float*)d_in[26];
    const float* clfb2 = (const float*)d_in[27];
    float* out = (float*)d_out;

    int nacc = in_sizes[0] / 64;
    int nmer = in_sizes[1] / 32;
    int E    = in_sizes[2] / 2;

    float *xa, *xm, *ya, *ym, *stat;
    uint32_t *xah, *xal, *xmh, *xml, *wh, *wl;
    int *rowptr, *csr, *deg, *cur, *bsum;
    cudaGetSymbolAddress((void**)&xa,     g_xa);
    cudaGetSymbolAddress((void**)&xm,     g_xm);
    cudaGetSymbolAddress((void**)&ya,     g_ya);
    cudaGetSymbolAddress((void**)&ym,     g_ym);
    cudaGetSymbolAddress((void**)&xah,    g_xah);
    cudaGetSymbolAddress((void**)&xal,    g_xal);
    cudaGetSymbolAddress((void**)&xmh,    g_xmh);
    cudaGetSymbolAddress((void**)&xml,    g_xml);
    cudaGetSymbolAddress((void**)&wh,     g_wh);
    cudaGetSymbolAddress((void**)&wl,     g_wl);
    cudaGetSymbolAddress((void**)&stat,   g_stat);
    cudaGetSymbolAddress((void**)&rowptr, g_rowptr);
    cudaGetSymbolAddress((void**)&csr,    g_csr);
    cudaGetSymbolAddress((void**)&deg,    g_deg);
    cudaGetSymbolAddress((void**)&cur,    g_cur);
    cudaGetSymbolAddress((void**)&bsum,   g_bsum);

    int* rp[3]  = {rowptr, rowptr + (NACC_MAX + 1), rowptr + 2 * (NACC_MAX + 1)};
    int* cs3[3] = {csr, csr + E_MAX, csr + 2 * E_MAX};
    int* dg[3]  = {deg, deg + NACC_MAX, deg + 2 * NACC_MAX};
    int* cu[3]  = {cur, cur + NACC_MAX, cur + 2 * NACC_MAX};
    int* bs[3]  = {bsum, bsum + 1024, bsum + 2 * 1024};
    int ndst[3] = {nmer, nacc, nacc};
    float* sum_a = stat;        float* sqs_a = stat + 128;
    float* sum_m = stat + 256;  float* sqs_m = stat + 384;

    // weight-split slot map: L0 -> 0,1,2 ; L1 -> 3,4,5 ; L2 -> 6 (rev), 7 (transfer)
    auto wslot = [&](int idx) { return (size_t)idx * 128 * 128; };

    // dynamic smem opt-in
    cudaFuncSetAttribute(proj_gemm, cudaFuncAttributeMaxDynamicSharedMemorySize, SMEM_PROJ);
    cudaFuncSetAttribute(sage_fused<128, false, true >, cudaFuncAttributeMaxDynamicSharedMemorySize, SMEM_FUSED);
    cudaFuncSetAttribute(sage_fused<128, false, false>, cudaFuncAttributeMaxDynamicSharedMemorySize, SMEM_FUSED);
    cudaFuncSetAttribute(sage_fused<128, true,  true >, cudaFuncAttributeMaxDynamicSharedMemorySize, SMEM_FUSED);
    cudaFuncSetAttribute(sage_fused<64,  false, false>, cudaFuncAttributeMaxDynamicSharedMemorySize, SMEM_FUSED);
    cudaFuncSetAttribute(sage_fused<64,  true,  true >, cudaFuncAttributeMaxDynamicSharedMemorySize, SMEM_FUSED);

    int agrid = (nacc + 127) / 128;
    int mgrid = (nmer + 127) / 128;

    // --- input projections (fp32 + split outputs) ---
    proj_gemm<<<agrid, 512, SMEM_PROJ>>>(nacc, 64, x_acc, projW_acc, projb_acc, xa, xah, xal);
    proj_gemm<<<mgrid, 512, SMEM_PROJ>>>(nmer, 32, x_mer, projW_mer, projb_mer, xm, xmh, xml);

    // --- CSR builds, phase-interleaved ---
    cudaMemsetAsync(deg, 0, 3 * (size_t)NACC_MAX * sizeof(int), 0);
    for (int t = 0; t < 3; t++)
        hist_kernel<<<(E + 255) / 256, 256>>>(ei[t], E, dg[t]);
    for (int t = 0; t < 3; t++)
        scan1<<<(ndst[t] + 1023) / 1024, 1024>>>(dg[t], ndst[t], rp[t], bs[t]);
    for (int t = 0; t < 3; t++)
        scan2<<<1, 1024>>>(bs[t], (ndst[t] + 1023) / 1024);
    for (int t = 0; t < 3; t++)
        scan3<<<(ndst[t] + 255) / 256, 256>>>(ndst[t], rp[t], bs[t]);
    for (int t = 0; t < 3; t++)
        cudaMemcpyAsync(cu[t], rp[t], (size_t)ndst[t] * sizeof(int),
                        cudaMemcpyDeviceToDevice, 0);
    for (int t = 0; t < 3; t++)
        scatter_kernel<<<(E + 255) / 256, 256>>>(ei[t], E, cu[t], cs3[t]);

    // --- all weight splits upfront ---
    int douts[3] = {128, 128, 64};
    {
        int slot = 0;
        for (int L = 0; L < 3; L++) {
            int DO = douts[L];
            for (int e = 0; e < 3; e++) {
                if (L == 2 && e == 0) continue;   // pays dead at L==2
                split_w<<<(DO * 128 + 255) / 256, 256>>>(
                    Wl[L] + (size_t)e * DO * 128, Wr[L] + (size_t)e * DO * 128,
                    wh + wslot(slot), wl + wslot(slot), DO);
                slot++;
            }
        }
    }

    // slot order emitted above: L0:{0,1,2}=slots0-2, L1:{0,1,2}=3-5, L2:{1,2}=6-7
    int slotOf[3][3] = {{0, 1, 2}, {3, 4, 5}, {-1, 6, 7}};

    for (int L = 0; L < 3; L++) {
        int DO = douts[L];

        // (a) pays: acc -> mer; emits merchant BN stats
        if (L < 2) {
            int s = slotOf[L][0];
            cudaMemsetAsync(sum_m, 0, 256 * sizeof(float), 0);
            sage_fused<128, false, true><<<mgrid, 512, SMEM_FUSED>>>(nmer,
                rp[0], cs3[0], xa, xmh, xml,
                wh + wslot(s), wl + wslot(s),
                bl[L] + 0 * DO, ym, sum_m, sqs_m);
        }

        // (b) rev: mer -> acc (no stats)
        {
            int s = slotOf[L][1];
            if (DO == 128)
                sage_fused<128, false, false><<<agrid, 512, SMEM_FUSED>>>(nacc,
                    rp[1], cs3[1], xm, xah, xal,
                    wh + wslot(s), wl + wslot(s),
                    bl[L] + 1 * DO, ya, nullptr, nullptr);
            else
                sage_fused<64, false, false><<<agrid, 512, SMEM_FUSED>>>(nacc,
                    rp[1], cs3[1], xm, xah, xal,
                    wh + wslot(s), wl + wslot(s),
                    bl[L] + 1 * DO, ya, nullptr, nullptr);
        }

        // (c) transfer: acc -> acc (HeteroConv +=); emits account BN stats
        {
            int s = slotOf[L][2];
            cudaMemsetAsync(sum_a, 0, 256 * sizeof(float), 0);
            if (DO == 128)
                sage_fused<128, true, true><<<agrid, 512, SMEM_FUSED>>>(nacc,
                    rp[2], cs3[2], xa, xah, xal,
                    wh + wslot(s), wl + wslot(s),
                    bl[L] + 2 * DO, ya, sum_a, sqs_a);
            else
                sage_fused<64, true, true><<<agrid, 512, SMEM_FUSED>>>(nacc,
                    rp[2], cs3[2], xa, xah, xal,
                    wh + wslot(s), wl + wslot(s),
                    bl[L] + 2 * DO, ya, sum_a, sqs_a);
        }

        // (d) BN account (+ReLU except last layer); emits split xdst for next layer
        bn_apply_kernel<<<2048, 256>>>(ya, xa, (L < 2) ? xah : nullptr, (L < 2) ? xal : nullptr,
                                       nacc, DO, sum_a, sqs_a,
                                       bng[L] + 0 * DO, bnb[L] + 0 * DO, (L < 2) ? 1 : 0);

        // (e) BN merchant (+ReLU); dead at L==2
        if (L < 2) {
            bn_apply_kernel<<<2048, 256>>>(ym, xm, xmh, xml, nmer, DO, sum_m, sqs_m,
                                           bng[L] + 1 * DO, bnb[L] + 1 * DO, 1);
        }
    }

    // --- classifier head on accounts ---
    classifier_kernel<<<(nacc + 7) / 8, 256>>>(xa, nacc, clfW1, clfb1, clfW2, clfb2, out);
}

// round 12
// speedup vs baseline: 1.0988x; 1.0988x over previous
#include <cuda_runtime.h>
#include <math.h>
#include <stdint.h>

#define NACC_MAX 200000
#define NMER_MAX 100000
#define E_MAX    500000

// ---------------- scratch (device globals; no allocations allowed) -------------
__device__ float    g_xa[(size_t)NACC_MAX * 128];
__device__ float    g_xm[(size_t)NMER_MAX * 128];
__device__ float    g_ya[(size_t)NACC_MAX * 128];
__device__ float    g_ym[(size_t)NMER_MAX * 128];
// pre-split bf16x2 hi/lo operand arrays ([n][64] uint32 = 64 k-pairs)
__device__ uint32_t g_aggh [(size_t)NACC_MAX * 64];   // rev -> acc
__device__ uint32_t g_aggl [(size_t)NACC_MAX * 64];
__device__ uint32_t g_agg2h[(size_t)NACC_MAX * 64];   // transfer -> acc
__device__ uint32_t g_agg2l[(size_t)NACC_MAX * 64];
__device__ uint32_t g_aggmh[(size_t)NMER_MAX * 64];   // pays -> mer
__device__ uint32_t g_aggml[(size_t)NMER_MAX * 64];
__device__ uint32_t g_xah[(size_t)NACC_MAX * 64];     // xdst split (accounts)
__device__ uint32_t g_xal[(size_t)NACC_MAX * 64];
__device__ uint32_t g_xmh[(size_t)NMER_MAX * 64];     // xdst split (merchants)
__device__ uint32_t g_xml[(size_t)NMER_MAX * 64];
__device__ uint32_t g_wh[8 * 128 * 128];              // pre-split weights, 8 slots
__device__ uint32_t g_wl[8 * 128 * 128];
__device__ int   g_rowptr[3][NACC_MAX + 1];
__device__ int   g_csr[3][E_MAX];
__device__ int   g_deg[3][NACC_MAX];
__device__ int   g_cur[3][NACC_MAX];
__device__ int   g_bsum[3][1024];
__device__ float g_stat[4 * 128];   // [sum_a | sqs_a | sum_m | sqs_m]

// ---------------- bf16x3 emulation helpers ---------------------------------------
__device__ __forceinline__ void split2(float2 v, uint32_t& h, uint32_t& l) {
    uint32_t u0 = __float_as_uint(v.x), u1 = __float_as_uint(v.y);
    h = __byte_perm(u0, u1, 0x7632);
    float r0 = v.x - __uint_as_float(u0 & 0xFFFF0000u);
    float r1 = v.y - __uint_as_float(u1 & 0xFFFF0000u);
    asm("cvt.rn.bf16x2.f32 %0, %1, %2;" : "=r"(l) : "f"(r1), "f"(r0));
}

__device__ __forceinline__ void mma_bf16(float* d, const uint32_t* a,
                                         uint32_t b0, uint32_t b1) {
    asm volatile(
        "mma.sync.aligned.m16n8k16.row.col.f32.bf16.bf16.f32 "
        "{%0,%1,%2,%3}, {%4,%5,%6,%7}, {%8,%9}, {%0,%1,%2,%3};"
        : "+f"(d[0]), "+f"(d[1]), "+f"(d[2]), "+f"(d[3])
        : "r"(a[0]), "r"(a[1]), "r"(a[2]), "r"(a[3]), "r"(b0), "r"(b1));
}

__device__ __forceinline__ uint32_t saddr(const void* p) {
    uint32_t a;
    asm("{ .reg .u64 t; cvta.to.shared.u64 t, %1; cvt.u32.u64 %0, t; }"
        : "=r"(a) : "l"(p));
    return a;
}

__device__ __forceinline__ void cp16(uint32_t dst, const void* src, bool pred) {
    asm volatile("cp.async.cg.shared.global [%0], [%1], 16, %2;"
                 :: "r"(dst), "l"(src), "r"(pred ? 16 : 0) : "memory");
}
__device__ __forceinline__ void cp_commit() {
    asm volatile("cp.async.commit_group;" ::: "memory");
}

// ---------------- CSR build ------------------------------------------------------
__global__ void hist_kernel(const int* __restrict__ ei, int E, int* __restrict__ deg) {
    int e = blockIdx.x * blockDim.x + threadIdx.x;
    if (e >= E) return;
    atomicAdd(&deg[ei[E + e]], 1);
}

__global__ void scan1(const int* __restrict__ deg, int n,
                      int* __restrict__ rowptr, int* __restrict__ bsum) {
    __shared__ int s[1024];
    int i = blockIdx.x * 1024 + threadIdx.x;
    int v = (i < n) ? deg[i] : 0;
    s[threadIdx.x] = v;
    __syncthreads();
    for (int off = 1; off < 1024; off <<= 1) {
        int t = (threadIdx.x >= off) ? s[threadIdx.x - off] : 0;
        __syncthreads();
        s[threadIdx.x] += t;
        __syncthreads();
    }
    if (i < n) rowptr[i + 1] = s[threadIdx.x];
    if (threadIdx.x == 1023) bsum[blockIdx.x] = s[1023];
}

__global__ void scan2(int* __restrict__ bsum, int nb) {
    __shared__ int s[1024];
    int v = (threadIdx.x < nb) ? bsum[threadIdx.x] : 0;
    s[threadIdx.x] = v;
    __syncthreads();
    for (int off = 1; off < 1024; off <<= 1) {
        int t = (threadIdx.x >= off) ? s[threadIdx.x - off] : 0;
        __syncthreads();
        s[threadIdx.x] += t;
        __syncthreads();
    }
    if (threadIdx.x < nb) bsum[threadIdx.x] = s[threadIdx.x] - v;  // exclusive
}

__global__ void scan3(int n, int* __restrict__ rowptr, const int* __restrict__ bsum,
                      int* __restrict__ cur) {
    int i = blockIdx.x * blockDim.x + threadIdx.x;
    if (i < n) {
        int v = rowptr[i + 1] + bsum[i >> 10];
        rowptr[i + 1] = v;
    }
    if (i == 0) rowptr[0] = 0;
    // second pass not needed: cur[i] = rowptr[i] (exclusive start) -- rowptr[i]
    // for i>0 was finalized by block (i-1)>>10 possibly in another block; do it
    // in scatter via rowptr read? Simpler: separate copy below.
}

__global__ void copy_cur(int n, const int* __restrict__ rowptr, int* __restrict__ cur) {
    int i = blockIdx.x * blockDim.x + threadIdx.x;
    if (i < n) cur[i] = rowptr[i];
}

__global__ void scatter_kernel(const int* __restrict__ ei, int E,
                               int* __restrict__ cur, int* __restrict__ csr) {
    int e = blockIdx.x * blockDim.x + threadIdx.x;
    if (e >= E) return;
    int src = ei[e], dst = ei[E + e];
    int pos = atomicAdd(&cur[dst], 1);
    csr[pos] = src;
}

// ---------------- weight split: [Wl|Wr] fp32 -> packed bf16x2 hi/lo --------------
__global__ void split_w(const float* __restrict__ W1, const float* __restrict__ W2,
                        uint32_t* __restrict__ Bh, uint32_t* __restrict__ Bl, int DO)
{
    int idx = blockIdx.x * 256 + threadIdx.x;
    if (idx >= DO * 128) return;
    int j = idx >> 7, p = idx & 127;
    const float* W = (p < 64) ? W1 + (size_t)j * 128 + 2 * p
                              : W2 + (size_t)j * 128 + 2 * (p - 64);
    uint32_t h, l;
    split2(make_float2(W[0], W[1]), h, l);
    Bh[idx] = h; Bl[idx] = l;
}

// ---------------- fused mean aggregation: writes pre-split hi/lo ----------------
__global__ __launch_bounds__(256)
void agg_all(int n0, const int* __restrict__ rp0, const int* __restrict__ cs0,
             const float* __restrict__ src0, uint32_t* __restrict__ oh0, uint32_t* __restrict__ ol0,
             int n1, const int* __restrict__ rp1, const int* __restrict__ cs1,
             const float* __restrict__ src1, uint32_t* __restrict__ oh1, uint32_t* __restrict__ ol1,
             int n2, const int* __restrict__ rp2, const int* __restrict__ cs2,
             const float* __restrict__ src2, uint32_t* __restrict__ oh2, uint32_t* __restrict__ ol2)
{
    int w = (blockIdx.x * blockDim.x + threadIdx.x) >> 5;
    int lane = threadIdx.x & 31;
    const int *rp, *cs; const float* src; uint32_t *oh, *ol; int d;
    if (w < n0)           { rp = rp0; cs = cs0; src = src0; oh = oh0; ol = ol0; d = w; }
    else if (w < n0 + n1) { rp = rp1; cs = cs1; src = src1; oh = oh1; ol = ol1; d = w - n0; }
    else if (w < n0 + n1 + n2) { rp = rp2; cs = cs2; src = src2; oh = oh2; ol = ol2; d = w - n0 - n1; }
    else return;

    int s = __ldg(&rp[d]), e = __ldg(&rp[d + 1]);
    float4 acc = make_float4(0.f, 0.f, 0.f, 0.f);
    int i = s;
    for (; i + 2 <= e; i += 2) {
        int s0 = __ldg(&cs[i]), s1 = __ldg(&cs[i + 1]);
        float4 v0 = __ldg(reinterpret_cast<const float4*>(src + (size_t)s0 * 128) + lane);
        float4 v1 = __ldg(reinterpret_cast<const float4*>(src + (size_t)s1 * 128) + lane);
        acc.x += v0.x + v1.x; acc.y += v0.y + v1.y;
        acc.z += v0.z + v1.z; acc.w += v0.w + v1.w;
    }
    if (i < e) {
        int s0 = __ldg(&cs[i]);
        float4 v0 = __ldg(reinterpret_cast<const float4*>(src + (size_t)s0 * 128) + lane);
        acc.x += v0.x; acc.y += v0.y; acc.z += v0.z; acc.w += v0.w;
    }
    float inv = 1.f / fmaxf((float)(e - s), 1.f);
    acc.x *= inv; acc.y *= inv; acc.z *= inv; acc.w *= inv;
    uint32_t h0, l0, h1, l1;
    split2(make_float2(acc.x, acc.y), h0, l0);
    split2(make_float2(acc.z, acc.w), h1, l1);
    *reinterpret_cast<uint2*>(oh + (size_t)d * 64 + 2 * lane) = make_uint2(h0, h1);
    *reinterpret_cast<uint2*>(ol + (size_t)d * 64 + 2 * lane) = make_uint2(l0, l1);
}

// ---------------- pre-split bf16x3 GEMM: zero-ALU mainloop (R10 proven) ----------
#define TILE_U 2560            // 128*20 uint32 per tile buffer
#define SMEM_GEMM ((6 * TILE_U + 512) * 4)

template<int DO, bool ACCUM, bool STATS>
__global__ __launch_bounds__(512)
void mma_gemm_ps(int n,
                 const uint32_t* __restrict__ Ah1, const uint32_t* __restrict__ Al1,
                 const uint32_t* __restrict__ Ah2, const uint32_t* __restrict__ Al2,
                 const uint32_t* __restrict__ Bh,  const uint32_t* __restrict__ Bl,
                 const float* __restrict__ bias, float* __restrict__ C,
                 float* __restrict__ gsum, float* __restrict__ gsqs)
{
    constexpr int NJ = DO / 32;
    extern __shared__ uint32_t smu[];
    uint32_t* AsBase = smu;                  // [3][128][20]
    uint32_t* BsBase = smu + 3 * TILE_U;     // [3][128][20]
    float* sBias = reinterpret_cast<float*>(smu + 6 * TILE_U);
    float* ssRow = sBias + 128;
    float* sCS   = ssRow + 128;
    float* sCQ   = sCS + 128;

    int tid = threadIdx.x, lane = tid & 31, warp = tid >> 5;
    int g = lane >> 2, t = lane & 3;
    int wm = warp & 3, wn = warp >> 2;
    int row0 = blockIdx.x * 128;

    if (tid < DO) {
        sBias[tid] = bias[tid];
        if (STATS) { sCS[tid] = 0.f; sCQ[tid] = 0.f; }
    }
    if (tid < 128) ssRow[tid] = 0.f;

    float acc[2][NJ][4];
#pragma unroll
    for (int i = 0; i < 2; i++)
#pragma unroll
        for (int j = 0; j < NJ; j++)
#pragma unroll
            for (int c = 0; c < 4; c++) acc[i][j][c] = 0.f;

    const int T = 16;   // K=256, BK=16

    auto load_tile = [&](int kt, int buf) {
        int m = tid >> 2, q = tid & 3;           // q: 0,1 = hi chunks; 2,3 = lo
        {
            bool isA2 = (kt >= 8);
            int pairBase = (isA2 ? kt - 8 : kt) * 8;
            const uint32_t* H = isA2 ? Ah2 : Ah1;
            const uint32_t* L = isA2 ? Al2 : Al1;
            int r = row0 + m;
            bool p = (r < n);
            int rc = p ? r : 0;
            const uint32_t* src = ((q < 2) ? H : L)
                                + (size_t)rc * 64 + pairBase + (q & 1) * 4;
            cp16(saddr(AsBase + buf * TILE_U + m * 20 + q * 4), src, p);
        }
        if (tid < DO * 4) {
            int j = tid >> 2, qb = tid & 3;
            const uint32_t* src = ((qb < 2) ? Bh : Bl)
                                + (size_t)j * 128 + kt * 8 + (qb & 1) * 4;
            cp16(saddr(BsBase + buf * TILE_U + j * 20 + qb * 4), src, true);
        }
    };

    auto compute = [&](int buf) {
        const uint32_t* As = AsBase + buf * TILE_U;
        const uint32_t* Bs = BsBase + buf * TILE_U;
        uint32_t ah[2][4], al[2][4];
#pragma unroll
        for (int i = 0; i < 2; i++) {
            int rb = wm * 32 + i * 16;
            ah[i][0] = As[(rb + g) * 20 + t];
            ah[i][1] = As[(rb + g + 8) * 20 + t];
            ah[i][2] = As[(rb + g) * 20 + t + 4];
            ah[i][3] = As[(rb + g + 8) * 20 + t + 4];
            al[i][0] = As[(rb + g) * 20 + t + 8];
            al[i][1] = As[(rb + g + 8) * 20 + t + 8];
            al[i][2] = As[(rb + g) * 20 + t + 12];
            al[i][3] = As[(rb + g + 8) * 20 + t + 12];
        }
#pragma unroll
        for (int j = 0; j < NJ; j++) {
            int nb = wn * (NJ * 8) + j * 8 + g;
            uint32_t bh0 = Bs[nb * 20 + t];
            uint32_t bh1 = Bs[nb * 20 + t + 4];
            uint32_t bl0 = Bs[nb * 20 + t + 8];
            uint32_t bl1 = Bs[nb * 20 + t + 12];
#pragma unroll
            for (int i = 0; i < 2; i++) {
                mma_bf16(acc[i][j], ah[i], bh0, bh1);
                mma_bf16(acc[i][j], ah[i], bl0, bl1);
                mma_bf16(acc[i][j], al[i], bh0, bh1);
            }
        }
    };

    load_tile(0, 0); cp_commit();
    load_tile(1, 1); cp_commit();
    for (int kt = 0; kt < T; kt++) {
        if (kt + 1 < T) asm volatile("cp.async.wait_group 1;" ::: "memory");
        else            asm volatile("cp.async.wait_group 0;" ::: "memory");
        __syncthreads();
        if (kt + 2 < T) { load_tile(kt + 2, (kt + 2) % 3); cp_commit(); }
        compute(kt % 3);
        __syncthreads();
    }

    // ---- epilogue: bias, row L2-norm, accumulate, fused BN stats ----
#pragma unroll
    for (int i = 0; i < 2; i++) {
        float ss0 = 0.f, ss1 = 0.f;
#pragma unroll
        for (int j = 0; j < NJ; j++) {
            int cb = wn * (NJ * 8) + j * 8 + t * 2;
            float b0 = sBias[cb], b1 = sBias[cb + 1];
            acc[i][j][0] += b0; acc[i][j][1] += b1;
            acc[i][j][2] += b0; acc[i][j][3] += b1;
            ss0 += acc[i][j][0] * acc[i][j][0] + acc[i][j][1] * acc[i][j][1];
            ss1 += acc[i][j][2] * acc[i][j][2] + acc[i][j][3] * acc[i][j][3];
        }
        ss0 += __shfl_xor_sync(0xffffffffu, ss0, 1);
        ss0 += __shfl_xor_sync(0xffffffffu, ss0, 2);
        ss1 += __shfl_xor_sync(0xffffffffu, ss1, 1);
        ss1 += __shfl_xor_sync(0xffffffffu, ss1, 2);
        if (t == 0) {
            atomicAdd(&ssRow[wm * 32 + i * 16 + g], ss0);
            atomicAdd(&ssRow[wm * 32 + i * 16 + g + 8], ss1);
        }
    }
    __syncthreads();

    float cs[NJ][2], cq[NJ][2];
    if (STATS) {
#pragma unroll
        for (int j = 0; j < NJ; j++) { cs[j][0] = cs[j][1] = cq[j][0] = cq[j][1] = 0.f; }
    }

#pragma unroll
    for (int i = 0; i < 2; i++) {
        int rl = wm * 32 + i * 16 + g;
        float s0 = 1.f / fmaxf(sqrtf(ssRow[rl]), 1e-12f);
        float s1 = 1.f / fmaxf(sqrtf(ssRow[rl + 8]), 1e-12f);
        int r0 = row0 + rl, r1 = r0 + 8;
#pragma unroll
        for (int j = 0; j < NJ; j++) {
            int cb = wn * (NJ * 8) + j * 8 + t * 2;
            if (r0 < n) {
                float2* p = reinterpret_cast<float2*>(C + (size_t)r0 * DO + cb);
                float2 v = make_float2(acc[i][j][0] * s0, acc[i][j][1] * s0);
                if (ACCUM) { float2 o = *p; v.x += o.x; v.y += o.y; }
                *p = v;
                if (STATS) {
                    cs[j][0] += v.x; cs[j][1] += v.y;
                    cq[j][0] += v.x * v.x; cq[j][1] += v.y * v.y;
                }
            }
            if (r1 < n) {
                float2* p = reinterpret_cast<float2*>(C + (size_t)r1 * DO + cb);
                float2 v = make_float2(acc[i][j][2] * s1, acc[i][j][3] * s1);
                if (ACCUM) { float2 o = *p; v.x += o.x; v.y += o.y; }
                *p = v;
                if (STATS) {
                    cs[j][0] += v.x; cs[j][1] += v.y;
                    cq[j][0] += v.x * v.x; cq[j][1] += v.y * v.y;
                }
            }
        }
    }

    if (STATS) {
#pragma unroll
        for (int j = 0; j < NJ; j++)
#pragma unroll
            for (int c = 0; c < 2; c++) {
                float s = cs[j][c], q = cq[j][c];
                s += __shfl_xor_sync(0xffffffffu, s, 4);
                s += __shfl_xor_sync(0xffffffffu, s, 8);
                s += __shfl_xor_sync(0xffffffffu, s, 16);
                q += __shfl_xor_sync(0xffffffffu, q, 4);
                q += __shfl_xor_sync(0xffffffffu, q, 8);
                q += __shfl_xor_sync(0xffffffffu, q, 16);
                if (g == 0) {
                    int cb = wn * (NJ * 8) + j * 8 + t * 2 + c;
                    atomicAdd(&sCS[cb], s);
                    atomicAdd(&sCQ[cb], q);
                }
            }
        __syncthreads();
        if (tid < DO) {
            atomicAdd(&gsum[tid], sCS[tid]);
            atomicAdd(&gsqs[tid], sCQ[tid]);
        }
    }
}

// ---------------- projection GEMM (split-in-loop, R10 proven) --------------------
__global__ __launch_bounds__(512)
void proj_gemm(int n, int K,
               const float* __restrict__ A1, const float* __restrict__ B1,
               const float* __restrict__ bias, float* __restrict__ C,
               uint32_t* __restrict__ Ch, uint32_t* __restrict__ Cl)
{
    constexpr int DO = 128, NJ = 4;
    extern __shared__ float smf[];
    float* AsBase = smf;
    float* BsBase = smf + 3 * TILE_U;
    float* sBias  = smf + 6 * TILE_U;

    int tid = threadIdx.x, lane = tid & 31, warp = tid >> 5;
    int g = lane >> 2, t = lane & 3;
    int wm = warp & 3, wn = warp >> 2;
    int row0 = blockIdx.x * 128;

    if (tid < DO) sBias[tid] = bias[tid];

    float acc[2][NJ][4];
#pragma unroll
    for (int i = 0; i < 2; i++)
#pragma unroll
        for (int j = 0; j < NJ; j++)
#pragma unroll
            for (int c = 0; c < 4; c++) acc[i][j][c] = 0.f;

    const int T = K >> 4;

    auto load_tile = [&](int kt, int buf) {
        {
            int m = tid >> 2, q = tid & 3, k = kt * 16 + q * 4;
            int r = row0 + m;
            bool p = (r < n);
            int rc = p ? r : 0;
            cp16(saddr(AsBase + buf * TILE_U + m * 20 + q * 4),
                 A1 + (size_t)rc * K + k, p);
        }
        {
            int j = tid >> 2, q = tid & 3, k = kt * 16 + q * 4;
            cp16(saddr(BsBase + buf * TILE_U + j * 20 + q * 4),
                 B1 + (size_t)j * K + k, true);
        }
    };

    auto compute = [&](int buf) {
        const float* As = AsBase + buf * TILE_U;
        const float* Bs = BsBase + buf * TILE_U;
        uint32_t ah[2][4], al[2][4];
#pragma unroll
        for (int i = 0; i < 2; i++) {
            int rb = wm * 32 + i * 16;
            float2 v0 = *reinterpret_cast<const float2*>(As + (rb + g) * 20 + 2 * t);
            float2 v1 = *reinterpret_cast<const float2*>(As + (rb + g + 8) * 20 + 2 * t);
            float2 v2 = *reinterpret_cast<const float2*>(As + (rb + g) * 20 + 2 * t + 8);
            float2 v3 = *reinterpret_cast<const float2*>(As + (rb + g + 8) * 20 + 2 * t + 8);
            split2(v0, ah[i][0], al[i][0]);
            split2(v1, ah[i][1], al[i][1]);
            split2(v2, ah[i][2], al[i][2]);
            split2(v3, ah[i][3], al[i][3]);
        }
#pragma unroll
        for (int j = 0; j < NJ; j++) {
            int nb = wn * (NJ * 8) + j * 8 + g;
            float2 w0 = *reinterpret_cast<const float2*>(Bs + nb * 20 + 2 * t);
            float2 w1 = *reinterpret_cast<const float2*>(Bs + nb * 20 + 2 * t + 8);
            uint32_t bh0, bl0, bh1, bl1;
            split2(w0, bh0, bl0);
            split2(w1, bh1, bl1);
#pragma unroll
            for (int i = 0; i < 2; i++) {
                mma_bf16(acc[i][j], ah[i], bh0, bh1);
                mma_bf16(acc[i][j], ah[i], bl0, bl1);
                mma_bf16(acc[i][j], al[i], bh0, bh1);
            }
        }
    };

    load_tile(0, 0); cp_commit();
    if (T > 1) { load_tile(1, 1); cp_commit(); }
    for (int kt = 0; kt < T; kt++) {
        if (kt + 1 < T) asm volatile("cp.async.wait_group 1;" ::: "memory");
        else            asm volatile("cp.async.wait_group 0;" ::: "memory");
        __syncthreads();
        if (kt + 2 < T) { load_tile(kt + 2, (kt + 2) % 3); cp_commit(); }
        compute(kt % 3);
        __syncthreads();
    }

    // epilogue: +bias, store fp32 + pre-split hi/lo
#pragma unroll
    for (int i = 0; i < 2; i++) {
        int rl = wm * 32 + i * 16 + g;
        int r0 = row0 + rl, r1 = r0 + 8;
#pragma unroll
        for (int j = 0; j < NJ; j++) {
            int cb = wn * (NJ * 8) + j * 8 + t * 2;
            float b0 = sBias[cb], b1 = sBias[cb + 1];
            if (r0 < n) {
                float2 v = make_float2(acc[i][j][0] + b0, acc[i][j][1] + b1);
                *reinterpret_cast<float2*>(C + (size_t)r0 * DO + cb) = v;
                uint32_t h, l; split2(v, h, l);
                Ch[(size_t)r0 * 64 + cb / 2] = h;
                Cl[(size_t)r0 * 64 + cb / 2] = l;
            }
            if (r1 < n) {
                float2 v = make_float2(acc[i][j][2] + b0, acc[i][j][3] + b1);
                *reinterpret_cast<float2*>(C + (size_t)r1 * DO + cb) = v;
                uint32_t h, l; split2(v, h, l);
                Ch[(size_t)r1 * 64 + cb / 2] = h;
                Cl[(size_t)r1 * 64 + cb / 2] = l;
            }
        }
    }
}

// ---------------- dual-segment BatchNorm apply (acc + mer in one launch) ---------
struct BNSeg {
    const float* X; float* Y;
    uint32_t* Yh; uint32_t* Yl;   // nullptr -> skip split output
    int n;
    const float* sum; const float* sqs;
    const float* g; const float* b;
    int relu;
};

__global__ void bn_dual(BNSeg s0, BNSeg s1, int d)
{
    int d4 = d >> 2;
    size_t t0 = (size_t)s0.n * d4;
    size_t t1 = (size_t)s1.n * d4;
    size_t total = t0 + t1;
    for (size_t gi = blockIdx.x * (size_t)blockDim.x + threadIdx.x; gi < total;
         gi += (size_t)gridDim.x * blockDim.x) {
        const BNSeg* S; size_t i;
        if (gi < t0) { S = &s0; i = gi; }
        else         { S = &s1; i = gi - t0; }
        int c = (int)(i % d4) * 4;
        float invn = 1.f / (float)S->n;
        float4 x = *(reinterpret_cast<const float4*>(S->X) + i);
        float4 y;
#pragma unroll
        for (int k = 0; k < 4; k++) {
            float mu = S->sum[c + k] * invn;
            float var = S->sqs[c + k] * invn - mu * mu;
            float xv = (&x.x)[k];
            float yv = (xv - mu) * rsqrtf(var + 1e-5f) * S->g[c + k] + S->b[c + k];
            if (S->relu) yv = fmaxf(yv, 0.f);
            (&y.x)[k] = yv;
        }
        *(reinterpret_cast<float4*>(S->Y) + i) = y;
        if (S->Yh) {
            uint32_t h0, l0, h1, l1;
            split2(make_float2(y.x, y.y), h0, l0);
            split2(make_float2(y.z, y.w), h1, l1);
            *reinterpret_cast<uint2*>(S->Yh + i * 2) = make_uint2(h0, h1);
            *reinterpret_cast<uint2*>(S->Yl + i * 2) = make_uint2(l0, l1);
        }
    }
}

// ---------------- fused classifier: relu(x@W1^T+b1)@W2^T+b2 --------------------
__global__ __launch_bounds__(256)
void classifier_kernel(const float* __restrict__ X, int n,
                       const float* __restrict__ W1, const float* __restrict__ b1,
                       const float* __restrict__ W2, const float* __restrict__ b2,
                       float* __restrict__ out)
{
    __shared__ float sW1[64 * 65];
    __shared__ float sW2[64];
    __shared__ float sb1[64];
    int tid = threadIdx.x;
    for (int i = tid; i < 64 * 64; i += 256) {
        int j = i >> 6, k = i & 63;
        sW1[j * 65 + k] = W1[i];
    }
    if (tid < 64) { sW2[tid] = W2[tid]; sb1[tid] = b1[tid]; }
    __syncthreads();

    int lane = tid & 31;
    int row = blockIdx.x * 8 + (tid >> 5);
    if (row >= n) return;
    float x0 = X[(size_t)row * 64 + lane];
    float x1 = X[(size_t)row * 64 + 32 + lane];
    float h0 = sb1[lane], h1 = sb1[lane + 32];
#pragma unroll
    for (int k = 0; k < 32; k++) {
        float xk = __shfl_sync(0xffffffffu, x0, k);
        h0 += xk * sW1[lane * 65 + k];
        h1 += xk * sW1[(lane + 32) * 65 + k];
    }
#pragma unroll
    for (int k = 0; k < 32; k++) {
        float xk = __shfl_sync(0xffffffffu, x1, k);
        h0 += xk * sW1[lane * 65 + 32 + k];
        h1 += xk * sW1[(lane + 32) * 65 + 32 + k];
    }
    h0 = fmaxf(h0, 0.f); h1 = fmaxf(h1, 0.f);
    float p = h0 * sW2[lane] + h1 * sW2[lane + 32];
#pragma unroll
    for (int off = 16; off; off >>= 1)
        p += __shfl_xor_sync(0xffffffffu, p, off);
    if (lane == 0) out[row] = p + b2[0];
}

// ---------------- kernel_launch -------------------------------------------------
extern "C" void kernel_launch(void* const* d_in, const int* in_sizes, int n_in,
                              void* d_out, int out_size)
{
    const float* x_acc      = (const float*)d_in[0];
    const float* x_mer      = (const float*)d_in[1];
    const int*   ei[3]      = {(const int*)d_in[2], (const int*)d_in[3], (const int*)d_in[4]};
    const float* projW_acc  = (const float*)d_in[5];
    const float* projb_acc  = (const float*)d_in[6];
    const float* projW_mer  = (const float*)d_in[7];
    const float* projb_mer  = (const float*)d_in[8];
    const float* Wl[3] = {(const float*)d_in[9],  (const float*)d_in[12], (const float*)d_in[15]};
    const float* bl[3] = {(const float*)d_in[10], (const float*)d_in[13], (const float*)d_in[16]};
    const float* Wr[3] = {(const float*)d_in[11], (const float*)d_in[14], (const float*)d_in[17]};
    const float* bng[3] = {(const float*)d_in[18], (const float*)d_in[20], (const float*)d_in[22]};
    const float* bnb[3] = {(const float*)d_in[19], (const float*)d_in[21], (const float*)d_in[23]};
    const float* clfW1 = (const float*)d_in[24];
    const float* clfb1 = (const float*)d_in[25];
    const float* clfW2 = (const float*)d_in[26];
    const float* clfb2 = (const float*)d_in[27];
    float* out = (float*)d_out;

    int nacc = in_sizes[0] / 64;
    int nmer = in_sizes[1] / 32;
    int E    = in_sizes[2] / 2;

    float *xa, *xm, *ya, *ym, *stat;
    uint32_t *aggh, *aggl, *agg2h, *agg2l, *aggmh, *aggml;
    uint32_t *xah, *xal, *xmh, *xml, *wh, *wl;
    int *rowptr, *csr, *deg, *cur, *bsum;
    cudaGetSymbolAddress((void**)&xa,     g_xa);
    cudaGetSymbolAddress((void**)&xm,     g_xm);
    cudaGetSymbolAddress((void**)&ya,     g_ya);
    cudaGetSymbolAddress((void**)&ym,     g_ym);
    cudaGetSymbolAddress((void**)&aggh,   g_aggh);
    cudaGetSymbolAddress((void**)&aggl,   g_aggl);
    cudaGetSymbolAddress((void**)&agg2h,  g_agg2h);
    cudaGetSymbolAddress((void**)&agg2l,  g_agg2l);
    cudaGetSymbolAddress((void**)&aggmh,  g_aggmh);
    cudaGetSymbolAddress((void**)&aggml,  g_aggml);
    cudaGetSymbolAddress((void**)&xah,    g_xah);
    cudaGetSymbolAddress((void**)&xal,    g_xal);
    cudaGetSymbolAddress((void**)&xmh,    g_xmh);
    cudaGetSymbolAddress((void**)&xml,    g_xml);
    cudaGetSymbolAddress((void**)&wh,     g_wh);
    cudaGetSymbolAddress((void**)&wl,     g_wl);
    cudaGetSymbolAddress((void**)&stat,   g_stat);
    cudaGetSymbolAddress((void**)&rowptr, g_rowptr);
    cudaGetSymbolAddress((void**)&csr,    g_csr);
    cudaGetSymbolAddress((void**)&deg,    g_deg);
    cudaGetSymbolAddress((void**)&cur,    g_cur);
    cudaGetSymbolAddress((void**)&bsum,   g_bsum);

    int* rp[3]  = {rowptr, rowptr + (NACC_MAX + 1), rowptr + 2 * (NACC_MAX + 1)};
    int* cs3[3] = {csr, csr + E_MAX, csr + 2 * E_MAX};
    int* dg[3]  = {deg, deg + NACC_MAX, deg + 2 * NACC_MAX};
    int* cu[3]  = {cur, cur + NACC_MAX, cur + 2 * NACC_MAX};
    int* bs[3]  = {bsum, bsum + 1024, bsum + 2 * 1024};
    int ndst[3] = {nmer, nacc, nacc};
    float* sum_a = stat;        float* sqs_a = stat + 128;
    float* sum_m = stat + 256;  float* sqs_m = stat + 384;

    auto wslot = [&](int idx) { return (size_t)idx * 128 * 128; };

    // dynamic smem opt-in
    cudaFuncSetAttribute(proj_gemm, cudaFuncAttributeMaxDynamicSharedMemorySize, SMEM_GEMM);
    cudaFuncSetAttribute(mma_gemm_ps<128, false, true >, cudaFuncAttributeMaxDynamicSharedMemorySize, SMEM_GEMM);
    cudaFuncSetAttribute(mma_gemm_ps<128, false, false>, cudaFuncAttributeMaxDynamicSharedMemorySize, SMEM_GEMM);
    cudaFuncSetAttribute(mma_gemm_ps<128, true,  true >, cudaFuncAttributeMaxDynamicSharedMemorySize, SMEM_GEMM);
    cudaFuncSetAttribute(mma_gemm_ps<64,  false, false>, cudaFuncAttributeMaxDynamicSharedMemorySize, SMEM_GEMM);
    cudaFuncSetAttribute(mma_gemm_ps<64,  true,  true >, cudaFuncAttributeMaxDynamicSharedMemorySize, SMEM_GEMM);

    int agrid = (nacc + 127) / 128;
    int mgrid = (nmer + 127) / 128;
    int douts[3] = {128, 128, 64};

    // --- input projections (fp32 + split outputs) ---
    proj_gemm<<<agrid, 512, SMEM_GEMM>>>(nacc, 64, x_acc, projW_acc, projb_acc, xa, xah, xal);
    proj_gemm<<<mgrid, 512, SMEM_GEMM>>>(nmer, 32, x_mer, projW_mer, projb_mer, xm, xmh, xml);

    // --- all weight splits upfront (off the layer-loop critical path) ---
    {
        int slot = 0;
        for (int L = 0; L < 3; L++) {
            int DO = douts[L];
            for (int e = 0; e < 3; e++) {
                if (L == 2 && e == 0) continue;   // pays dead at L==2
                split_w<<<(DO * 128 + 255) / 256, 256>>>(
                    Wl[L] + (size_t)e * DO * 128, Wr[L] + (size_t)e * DO * 128,
                    wh + wslot(slot), wl + wslot(slot), DO);
                slot++;
            }
        }
    }
    int slotOf[3][3] = {{0, 1, 2}, {3, 4, 5}, {-1, 6, 7}};

    // --- CSR builds, phase-interleaved ---
    cudaMemsetAsync(deg, 0, 3 * (size_t)NACC_MAX * sizeof(int), 0);
    for (int t = 0; t < 3; t++)
        hist_kernel<<<(E + 255) / 256, 256>>>(ei[t], E, dg[t]);
    for (int t = 0; t < 3; t++)
        scan1<<<(ndst[t] + 1023) / 1024, 1024>>>(dg[t], ndst[t], rp[t], bs[t]);
    for (int t = 0; t < 3; t++)
        scan2<<<1, 1024>>>(bs[t], (ndst[t] + 1023) / 1024);
    for (int t = 0; t < 3; t++)
        scan3<<<(ndst[t] + 255) / 256, 256>>>(ndst[t], rp[t], bs[t], cu[t]);
    for (int t = 0; t < 3; t++)
        copy_cur<<<(ndst[t] + 255) / 256, 256>>>(ndst[t], rp[t], cu[t]);
    for (int t = 0; t < 3; t++)
        scatter_kernel<<<(E + 255) / 256, 256>>>(ei[t], E, cu[t], cs3[t]);

    for (int L = 0; L < 3; L++) {
        int DO = douts[L];
        int n0 = (L < 2) ? nmer : 0;   // pays dead at L==2

        // --- all aggregations for this layer in one launch (pre-split outputs) ---
        int twarp = n0 + nacc + nacc;
        agg_all<<<(twarp * 32 + 255) / 256, 256>>>(
            n0,   rp[0], cs3[0], xa, aggmh, aggml,
            nacc, rp[1], cs3[1], xm, aggh,  aggl,
            nacc, rp[2], cs3[2], xa, agg2h, agg2l);

        // --- zero all stats for this layer in one memset ---
        cudaMemsetAsync(stat, 0, 512 * sizeof(float), 0);

        // (a) pays: acc -> mer; emits merchant BN stats
        if (L < 2) {
            int s = slotOf[L][0];
            mma_gemm_ps<128, false, true><<<mgrid, 512, SMEM_GEMM>>>(nmer,
                aggmh, aggml, xmh, xml, wh + wslot(s), wl + wslot(s),
                bl[L] + 0 * DO, ym, sum_m, sqs_m);
        }

        // (b) rev: mer -> acc (no stats)
        {
            int s = slotOf[L][1];
            if (DO == 128)
                mma_gemm_ps<128, false, false><<<agrid, 512, SMEM_GEMM>>>(nacc,
                    aggh, aggl, xah, xal, wh + wslot(s), wl + wslot(s),
                    bl[L] + 1 * DO, ya, nullptr, nullptr);
            else
                mma_gemm_ps<64, false, false><<<agrid, 512, SMEM_GEMM>>>(nacc,
                    aggh, aggl, xah, xal, wh + wslot(s), wl + wslot(s),
                    bl[L] + 1 * DO, ya, nullptr, nullptr);
        }

        // (c) transfer: acc -> acc (HeteroConv +=); emits account BN stats
        {
            int s = slotOf[L][2];
            if (DO == 128)
                mma_gemm_ps<128, true, true><<<agrid, 512, SMEM_GEMM>>>(nacc,
                    agg2h, agg2l, xah, xal, wh + wslot(s), wl + wslot(s),
                    bl[L] + 2 * DO, ya, sum_a, sqs_a);
            else
                mma_gemm_ps<64, true, true><<<agrid, 512, SMEM_GEMM>>>(nacc,
                    agg2h, agg2l, xah, xal, wh + wslot(s), wl + wslot(s),
                    bl[L] + 2 * DO, ya, sum_a, sqs_a);
        }

        // (d) BN both node types in ONE launch (+ReLU except last layer for acc)
        {
            BNSeg sa = {ya, xa, (L < 2) ? xah : nullptr, (L < 2) ? xal : nullptr,
                        nacc, sum_a, sqs_a, bng[L] + 0 * DO, bnb[L] + 0 * DO,
                        (L < 2) ? 1 : 0};
            BNSeg sm = {ym, xm, xmh, xml, (L < 2) ? nmer : 0,
                        sum_m, sqs_m, bng[L] + 1 * DO, bnb[L] + 1 * DO, 1};
            bn_dual<<<2048, 256>>>(sa, sm, DO);
        }
    }

    // --- classifier head on accounts ---
    classifier_kernel<<<(nacc + 7) / 8, 256>>>(xa, nacc, clfW1, clfb1, clfW2, clfb2, out);
}